// round 4
// baseline (speedup 1.0000x reference)
#include <cuda_runtime.h>
#include <cstdint>

#define NNODES 10000
#define NEDGES 160000
#define INCH   256
#define HID    512

// ---------------- device scratch (referenced ONLY from device code) ----------------
__device__ float g_h   [NNODES * HID];
__device__ float g_h2  [NNODES * HID];
__device__ float g_msg [NNODES * HID];
__device__ float g_aggr[NNODES * HID];
__device__ int   g_deg   [NNODES];
__device__ int   g_rowptr[NNODES + 1];
__device__ int   g_cursor[NNODES];
__device__ int   g_col   [NEDGES];
__device__ int   g_is64;          // 1 if edge_index is int64 on device, 0 if int32

// buffer selector: 1=g_h 2=g_h2 3=g_msg 4=g_aggr
__device__ __forceinline__ float* sel_buf(int s) {
    switch (s) {
        case 1: return g_h;
        case 2: return g_h2;
        case 3: return g_msg;
        default: return g_aggr;
    }
}

// Read edge endpoint `which` (0=src,1=dst) of edge e, robust to int32/int64 storage.
__device__ __forceinline__ int edge_at(const void* p, int which, int e) {
    long long v;
    if (g_is64) v = ((const long long*)p)[(size_t)which * NEDGES + e];
    else        v = ((const int*)p)[(size_t)which * NEDGES + e];
    int iv = (int)v;
    if (iv < 0) iv = 0;
    if (iv >= NNODES) iv = NNODES - 1;
    return iv;
}

// ---------------- dtype sniffer ----------------
// int64 values in [0, 2^32): odd 32-bit words are all zero.
// int32 node ids in [0,10000): odd words are ids (P[all zero] ~ 0 over 2048 samples).
__global__ void sniff_kernel(const unsigned int* __restrict__ w) {
    __shared__ int nz;
    if (threadIdx.x == 0) nz = 0;
    __syncthreads();
    int c = 0;
    for (int i = threadIdx.x; i < 2048; i += blockDim.x)
        if (w[2 * i + 1] != 0u) c++;
    if (c) atomicAdd(&nz, c);
    __syncthreads();
    if (threadIdx.x == 0) g_is64 = (nz == 0) ? 1 : 0;
}

// ---------------- CSR build ----------------
__global__ void zero_deg_kernel() {
    int i = blockIdx.x * blockDim.x + threadIdx.x;
    if (i < NNODES) g_deg[i] = 0;
}

__global__ void hist_kernel(const void* __restrict__ eidx, int nE) {
    int e = blockIdx.x * blockDim.x + threadIdx.x;
    if (e < nE) atomicAdd(&g_deg[edge_at(eidx, 1, e)], 1);
}

__global__ void scan_kernel(int n, int nE) {
    __shared__ int sums[1024];
    int tid = threadIdx.x;
    const int CH = (n + 1023) / 1024;
    int start = tid * CH;
    int s = 0;
    for (int i = 0; i < CH; i++) {
        int idx = start + i;
        if (idx < n) s += g_deg[idx];
    }
    sums[tid] = s;
    __syncthreads();
    if (tid == 0) {
        int run = 0;
        for (int i = 0; i < 1024; i++) { int t = sums[i]; sums[i] = run; run += t; }
    }
    __syncthreads();
    int run = sums[tid];
    for (int i = 0; i < CH; i++) {
        int idx = start + i;
        if (idx < n) { g_rowptr[idx] = run; g_cursor[idx] = run; run += g_deg[idx]; }
    }
    if (tid == 0) g_rowptr[n] = nE;
}

__global__ void fill_kernel(const void* __restrict__ eidx, int nE) {
    int e = blockIdx.x * blockDim.x + threadIdx.x;
    if (e < nE) {
        int d = edge_at(eidx, 1, e);
        int pos = atomicAdd(&g_cursor[d], 1);
        g_col[pos] = edge_at(eidx, 0, e);
    }
}

// ---------------- SGEMM: C = relu?(concat_K(A0,A1) @ B + bias) ----------------
// A0: external pointer if a0ext != nullptr, else device buffer sel a0sel.
// A1: g_aggr if useA1 (K1=512), else unused (K1=0).
// B: [K0+K1, 512] row-major. C: device buffer sel csel, [M, 512] row-major.
// Block tile 128x128, BK=8, 256 threads, 8x8 microtile per thread.
__global__ void __launch_bounds__(256)
gemm_bias_relu(const float* __restrict__ a0ext, int a0sel,
               int useA1,
               int K0, int K1,
               const float* __restrict__ B, const float* __restrict__ bias,
               int csel, int M, int doRelu)
{
    const int N = HID;
    const int K = K0 + K1;
    const float* A0 = a0ext ? a0ext : sel_buf(a0sel);
    const float* A1 = useA1 ? g_aggr : nullptr;
    float* C = sel_buf(csel);

    __shared__ float As[8][128];
    __shared__ float Bs[8][128];

    int tid = threadIdx.x;
    int tx = tid & 15;
    int ty = tid >> 4;
    int row0 = blockIdx.y * 128;
    int col0 = blockIdx.x * 128;

    float acc[8][8];
#pragma unroll
    for (int i = 0; i < 8; i++)
#pragma unroll
        for (int j = 0; j < 8; j++) acc[i][j] = 0.f;

    int arow = tid >> 1;
    int akk  = (tid & 1) * 4;
    int brow = tid >> 5;
    int bcol = (tid & 31) * 4;

    for (int kt = 0; kt < K; kt += 8) {
        int grow = row0 + arow;
        int gk = kt + akk;
        float4 av = make_float4(0.f, 0.f, 0.f, 0.f);
        if (grow < M) {
            if (gk < K0) av = *(const float4*)(A0 + (size_t)grow * K0 + gk);
            else         av = *(const float4*)(A1 + (size_t)grow * K1 + (gk - K0));
        }
        As[akk + 0][arow] = av.x;
        As[akk + 1][arow] = av.y;
        As[akk + 2][arow] = av.z;
        As[akk + 3][arow] = av.w;

        float4 bv = *(const float4*)(B + (size_t)(kt + brow) * N + col0 + bcol);
        *(float4*)(&Bs[brow][bcol]) = bv;
        __syncthreads();

#pragma unroll
        for (int kk = 0; kk < 8; kk++) {
            float a[8], b[8];
#pragma unroll
            for (int i = 0; i < 8; i++) a[i] = As[kk][ty * 8 + i];
#pragma unroll
            for (int j = 0; j < 8; j++) b[j] = Bs[kk][tx * 8 + j];
#pragma unroll
            for (int i = 0; i < 8; i++)
#pragma unroll
                for (int j = 0; j < 8; j++) acc[i][j] += a[i] * b[j];
        }
        __syncthreads();
    }

#pragma unroll
    for (int i = 0; i < 8; i++) {
        int r = row0 + ty * 8 + i;
        if (r >= M) continue;
#pragma unroll
        for (int j = 0; j < 8; j += 4) {
            int c = col0 + tx * 8 + j;
            float4 bv = *(const float4*)(bias + c);
            float4 v;
            v.x = acc[i][j + 0] + bv.x;
            v.y = acc[i][j + 1] + bv.y;
            v.z = acc[i][j + 2] + bv.z;
            v.w = acc[i][j + 3] + bv.w;
            if (doRelu) {
                v.x = fmaxf(v.x, 0.f); v.y = fmaxf(v.y, 0.f);
                v.z = fmaxf(v.z, 0.f); v.w = fmaxf(v.w, 0.f);
            }
            *(float4*)(C + (size_t)r * N + c) = v;
        }
    }
}

// ---------------- aggregation: g_aggr[d,:] = sum_{e: dst=d} g_msg[src(e),:] ----------------
__global__ void __launch_bounds__(128)
aggregate_kernel()
{
    int d = blockIdx.x;
    int t = threadIdx.x;            // 128 threads, each owns one float4 (512 ch)
    float4 acc = make_float4(0.f, 0.f, 0.f, 0.f);
    int beg = g_rowptr[d], end = g_rowptr[d + 1];
    for (int j = beg; j < end; j++) {
        int s = g_col[j];
        float4 v = *(const float4*)(g_msg + (size_t)s * HID + t * 4);
        acc.x += v.x; acc.y += v.y; acc.z += v.z; acc.w += v.w;
    }
    *(float4*)(g_aggr + (size_t)d * HID + t * 4) = acc;
}

// ---------------- output projection: out[i] = g_h[i,:] . W_out + b_out ----------------
__global__ void out_kernel(const float* __restrict__ Wout,
                           const float* __restrict__ bout,
                           float* __restrict__ out, int n)
{
    int warp = (blockIdx.x * blockDim.x + threadIdx.x) >> 5;
    int lane = threadIdx.x & 31;
    if (warp >= n) return;
    const float* hr = g_h + (size_t)warp * HID;
    float s = 0.f;
#pragma unroll 4
    for (int k = lane; k < HID; k += 32) s += hr[k] * Wout[k];
#pragma unroll
    for (int o = 16; o; o >>= 1) s += __shfl_down_sync(0xffffffffu, s, o);
    if (lane == 0) out[warp] = s + bout[0];
}

// ---------------- launcher ----------------
extern "C" void kernel_launch(void* const* d_in, const int* in_sizes, int n_in,
                              void* d_out, int out_size)
{
    const float* x     = (const float*)d_in[0];           // [10000,256]
    const void*  eidx  = d_in[1];                         // [2,160000] int32 or int64
    const float* W_in  = (const float*)d_in[2];           // [256,512]
    const float* b_in  = (const float*)d_in[3];           // [512]
    const float* msg_W = (const float*)d_in[4];           // [2,512,512]
    const float* msg_b = (const float*)d_in[5];           // [2,512]
    const float* upd_W = (const float*)d_in[6];           // [2,1024,512]
    const float* upd_b = (const float*)d_in[7];           // [2,512]
    const float* W_out = (const float*)d_in[8];           // [512,1]
    const float* b_out = (const float*)d_in[9];           // [1]
    float* out = (float*)d_out;

    // ---- dtype sniff + CSR build (shared by both layers) ----
    sniff_kernel<<<1, 256>>>((const unsigned int*)eidx);
    zero_deg_kernel<<<(NNODES + 255) / 256, 256>>>();
    hist_kernel<<<(NEDGES + 255) / 256, 256>>>(eidx, NEDGES);
    scan_kernel<<<1, 1024>>>(NNODES, NEDGES);
    fill_kernel<<<(NEDGES + 255) / 256, 256>>>(eidx, NEDGES);

    dim3 ggrid(HID / 128, (NNODES + 127) / 128);

    // ---- input embedding: g_h = relu(x @ W_in + b_in) ----
    gemm_bias_relu<<<ggrid, 256>>>(x, 0, 0, INCH, 0, W_in, b_in, /*c=*/1, NNODES, 1);

    // buffer selectors: 1=g_h 2=g_h2 3=g_msg 4=g_aggr
    int cur = 1, nxt = 2;
    for (int l = 0; l < 2; l++) {
        const float* mW = msg_W + (size_t)l * HID * HID;
        const float* mb = msg_b + (size_t)l * HID;
        const float* uW = upd_W + (size_t)l * 2 * HID * HID;
        const float* ub = upd_b + (size_t)l * HID;

        // node-level messages (gather commutes with linear+bias+relu)
        gemm_bias_relu<<<ggrid, 256>>>(nullptr, cur, 0, HID, 0, mW, mb, /*c=*/3, NNODES, 1);
        // scatter-add over destinations via CSR gather
        aggregate_kernel<<<NNODES, 128>>>();
        // update: relu([h, aggr] @ upd_W + b) as split-K GEMM
        gemm_bias_relu<<<ggrid, 256>>>(nullptr, cur, 1, HID, HID, uW, ub, /*c=*/nxt, NNODES, 1);

        int t = cur; cur = nxt; nxt = t;
    }
    // after 2 layers cur == 1 (g_h), which out_kernel reads.

    // ---- output projection ----
    out_kernel<<<(NNODES * 32 + 255) / 256, 256>>>(W_out, b_out, out, NNODES);
}

// round 7
// speedup vs baseline: 2.2026x; 2.2026x over previous
#include <cuda_runtime.h>
#include <cuda_bf16.h>
#include <cstdint>

#define NNODES 10000
#define NEDGES 160000
#define INCH   256
#define HID    512
#define LDA    1024          // A staging row stride (bf16 elems)

// ---------------- device scratch (referenced ONLY from device code) ----------------
__device__ float g_h   [NNODES * HID];
__device__ float g_h2  [NNODES * HID];
__device__ float g_msg [NNODES * HID];
__device__ float g_aggr[NNODES * HID];
__device__ __nv_bfloat16 g_ahi[NNODES * LDA];
__device__ __nv_bfloat16 g_alo[NNODES * LDA];
__device__ __nv_bfloat16 g_whi[HID * 1024];   // transposed weights [512, K]
__device__ __nv_bfloat16 g_wlo[HID * 1024];
__device__ int   g_deg   [NNODES];
__device__ int   g_rowptr[NNODES + 1];
__device__ int   g_cursor[NNODES];
__device__ int   g_col   [NEDGES];
__device__ int   g_is64;

__device__ __forceinline__ float* sel_buf(int s) {
    switch (s) {
        case 1: return g_h;
        case 2: return g_h2;
        case 3: return g_msg;
        default: return g_aggr;
    }
}

__device__ __forceinline__ uint32_t smem_u32(const void* p) {
    uint32_t a;
    asm("{ .reg .u64 t; cvta.to.shared.u64 t, %1; cvt.u32.u64 %0, t; }" : "=r"(a) : "l"(p));
    return a;
}
#define SWZ128(o) ((o) ^ (((o) >> 3) & 0x70))

#define LDSM4(r, addr)                                                        \
    asm volatile("ldmatrix.sync.aligned.m8n8.x4.shared.b16 {%0,%1,%2,%3}, [%4];" \
        : "=r"((r)[0]), "=r"((r)[1]), "=r"((r)[2]), "=r"((r)[3]) : "r"(addr))

#define MMA_BF16(d, a, b)                                                     \
    asm volatile("mma.sync.aligned.m16n8k16.row.col.f32.bf16.bf16.f32 "       \
        "{%0,%1,%2,%3}, {%4,%5,%6,%7}, {%8,%9}, {%0,%1,%2,%3};"               \
        : "+f"((d)[0]), "+f"((d)[1]), "+f"((d)[2]), "+f"((d)[3])              \
        : "r"((a)[0]), "r"((a)[1]), "r"((a)[2]), "r"((a)[3]),                 \
          "r"((b)[0]), "r"((b)[1]))

// ---------------- edge index (dtype-robust) ----------------
__device__ __forceinline__ int edge_at(const void* p, int which, int e) {
    long long v;
    if (g_is64) v = ((const long long*)p)[(size_t)which * NEDGES + e];
    else        v = ((const int*)p)[(size_t)which * NEDGES + e];
    int iv = (int)v;
    if (iv < 0) iv = 0;
    if (iv >= NNODES) iv = NNODES - 1;
    return iv;
}

__global__ void sniff_kernel(const unsigned int* __restrict__ w) {
    __shared__ int nz;
    if (threadIdx.x == 0) nz = 0;
    __syncthreads();
    int c = 0;
    for (int i = threadIdx.x; i < 2048; i += blockDim.x)
        if (w[2 * i + 1] != 0u) c++;
    if (c) atomicAdd(&nz, c);
    __syncthreads();
    if (threadIdx.x == 0) g_is64 = (nz == 0) ? 1 : 0;
}

// ---------------- CSR build ----------------
__global__ void zero_deg_kernel() {
    int i = blockIdx.x * blockDim.x + threadIdx.x;
    if (i < NNODES) g_deg[i] = 0;
}
__global__ void hist_kernel(const void* __restrict__ eidx, int nE) {
    int e = blockIdx.x * blockDim.x + threadIdx.x;
    if (e < nE) atomicAdd(&g_deg[edge_at(eidx, 1, e)], 1);
}
__global__ void scan_kernel(int n, int nE) {
    __shared__ int wsum[32];
    int tid = threadIdx.x;                 // 1024 threads
    const int CH = (n + 1023) / 1024;
    int start = tid * CH;
    int s = 0;
    for (int i = 0; i < CH; i++) {
        int idx = start + i;
        if (idx < n) s += g_deg[idx];
    }
    int lane = tid & 31, warp = tid >> 5;
    int v = s;
#pragma unroll
    for (int o = 1; o < 32; o <<= 1) {
        int t = __shfl_up_sync(0xffffffffu, v, o);
        if (lane >= o) v += t;
    }
    if (lane == 31) wsum[warp] = v;
    __syncthreads();
    if (warp == 0) {
        int w = wsum[lane];
#pragma unroll
        for (int o = 1; o < 32; o <<= 1) {
            int t = __shfl_up_sync(0xffffffffu, w, o);
            if (lane >= o) w += t;
        }
        wsum[lane] = w;
    }
    __syncthreads();
    int excl = v - s + (warp ? wsum[warp - 1] : 0);
    int run = excl;
    for (int i = 0; i < CH; i++) {
        int idx = start + i;
        if (idx < n) { g_rowptr[idx] = run; g_cursor[idx] = run; run += g_deg[idx]; }
    }
    if (tid == 1023) g_rowptr[n] = nE;
}
__global__ void fill_kernel(const void* __restrict__ eidx, int nE) {
    int e = blockIdx.x * blockDim.x + threadIdx.x;
    if (e < nE) {
        int d = edge_at(eidx, 1, e);
        int pos = atomicAdd(&g_cursor[d], 1);
        g_col[pos] = edge_at(eidx, 0, e);
    }
}

// ---------------- operand conversion ----------------
__global__ void conv_A(const float* __restrict__ ext, int asel, int c0, int ncols, int M) {
    const float* src = ext ? ext : sel_buf(asel);
    int nq = ncols >> 2;
    int i = blockIdx.x * blockDim.x + threadIdx.x;
    if (i >= M * nq) return;
    int row = i / nq;
    int c = (i - row * nq) * 4;
    float4 v = *(const float4*)(src + (size_t)row * ncols + c);
    __nv_bfloat16 hx = __float2bfloat16_rn(v.x), hy = __float2bfloat16_rn(v.y);
    __nv_bfloat16 hz = __float2bfloat16_rn(v.z), hw = __float2bfloat16_rn(v.w);
    __nv_bfloat16 lx = __float2bfloat16_rn(v.x - __bfloat162float(hx));
    __nv_bfloat16 ly = __float2bfloat16_rn(v.y - __bfloat162float(hy));
    __nv_bfloat16 lz = __float2bfloat16_rn(v.z - __bfloat162float(hz));
    __nv_bfloat16 lw = __float2bfloat16_rn(v.w - __bfloat162float(hw));
    size_t o = (size_t)row * LDA + c0 + c;
    __nv_bfloat162* ph = (__nv_bfloat162*)(g_ahi + o);
    __nv_bfloat162* pl = (__nv_bfloat162*)(g_alo + o);
    ph[0] = __nv_bfloat162(hx, hy); ph[1] = __nv_bfloat162(hz, hw);
    pl[0] = __nv_bfloat162(lx, ly); pl[1] = __nv_bfloat162(lz, lw);
}

// W: fp32 [K, 512] -> transposed hi/lo bf16 [512, K]
__global__ void conv_W(const float* __restrict__ W, int K) {
    __shared__ float tile[32][33];
    int n0 = blockIdx.x * 32, k0 = blockIdx.y * 32;
    int tx = threadIdx.x, ty = threadIdx.y;        // (32, 8)
    for (int i = ty; i < 32; i += 8)
        tile[i][tx] = W[(size_t)(k0 + i) * HID + n0 + tx];
    __syncthreads();
    for (int i = ty; i < 32; i += 8) {
        float v = tile[tx][i];                      // = W[k0+tx][n0+i]
        __nv_bfloat16 h = __float2bfloat16_rn(v);
        __nv_bfloat16 l = __float2bfloat16_rn(v - __bfloat162float(h));
        size_t o = (size_t)(n0 + i) * K + k0 + tx;
        g_whi[o] = h; g_wlo[o] = l;
    }
}

// ---------------- mma.sync GEMM: C[:,512] = relu?(A(split bf16) @ W(split bf16)^T + bias) ----------------
// Block tile 128x128, BK=64, 256 threads (8 warps, warp tile 32x64).
// SMEM (single stage, 64KB): Ahi 16K | Alo 16K | Bhi 16K | Blo 16K, SW128 swizzled.
#define GSMEM 65536

__global__ void __launch_bounds__(256)
gemm_mma(int K, const float* __restrict__ bias, int csel, int M, int doRelu)
{
    extern __shared__ char smem[];
    uint32_t sb = smem_u32(smem);
    float* C = sel_buf(csel);
    int tid = threadIdx.x, lane = tid & 31, wid = tid >> 5;
    int warp_m = wid & 3, warp_n = wid >> 2;      // 4 x 2 warps -> 128 x 128
    int m0 = blockIdx.y * 128, n0 = blockIdx.x * 128;

    float c[2][8][4];
#pragma unroll
    for (int mt = 0; mt < 2; mt++)
#pragma unroll
        for (int nt = 0; nt < 8; nt++)
#pragma unroll
            for (int j = 0; j < 4; j++) c[mt][nt][j] = 0.f;

    const int q = lane >> 3, li = lane & 7;
    int NKB = K >> 6;

    for (int kb = 0; kb < NKB; kb++) {
        __syncthreads();
        // load chunk: A/B hi+lo, 128 rows x 64 bf16 each, SW128 swizzle
#pragma unroll
        for (int t = 0; t < 4; t++) {
            int i = tid + t * 256;
            int row = i >> 3, grp = i & 7;
            int gr = m0 + row; if (gr >= M) gr = M - 1;
            size_t aoff = (size_t)gr * LDA + kb * 64 + grp * 8;
            size_t boff = (size_t)(n0 + row) * K + kb * 64 + grp * 8;
            uint32_t sw = SWZ128(row * 128 + grp * 16);
            *(uint4*)(smem + sw)          = *(const uint4*)(g_ahi + aoff);
            *(uint4*)(smem + 16384 + sw)  = *(const uint4*)(g_alo + aoff);
            *(uint4*)(smem + 32768 + sw)  = *(const uint4*)(g_whi + boff);
            *(uint4*)(smem + 49152 + sw)  = *(const uint4*)(g_wlo + boff);
        }
        __syncthreads();

#pragma unroll
        for (int s = 0; s < 4; s++) {
            uint32_t ah[2][4], al[2][4], bh[8][2], bl[8][2];
            // A fragments (m16xk16): matrices = {m0-7 klo, m8-15 klo, m0-7 khi, m8-15 khi}
#pragma unroll
            for (int mt = 0; mt < 2; mt++) {
                int row = warp_m * 32 + mt * 16 + ((q & 1) << 3) + li;
                int grp = s * 2 + (q >> 1);
                uint32_t ad = sb + SWZ128(row * 128 + grp * 16);
                LDSM4(ah[mt], ad);
                LDSM4(al[mt], ad + 16384);
            }
            // B fragments, pairs of n8-tiles per x4
#pragma unroll
            for (int np = 0; np < 4; np++) {
                int nrow = warp_n * 64 + np * 16 + ((q >> 1) << 3) + li;
                int grp = s * 2 + (q & 1);
                uint32_t bd = sb + 32768 + SWZ128(nrow * 128 + grp * 16);
                uint32_t r[4];
                LDSM4(r, bd);
                bh[np*2][0] = r[0]; bh[np*2][1] = r[1];
                bh[np*2+1][0] = r[2]; bh[np*2+1][1] = r[3];
                LDSM4(r, bd + 16384);
                bl[np*2][0] = r[0]; bl[np*2][1] = r[1];
                bl[np*2+1][0] = r[2]; bl[np*2+1][1] = r[3];
            }
#pragma unroll
            for (int mt = 0; mt < 2; mt++)
#pragma unroll
                for (int nt = 0; nt < 8; nt++) {
                    MMA_BF16(c[mt][nt], ah[mt], bh[nt]);
                    MMA_BF16(c[mt][nt], ah[mt], bl[nt]);
                    MMA_BF16(c[mt][nt], al[mt], bh[nt]);
                }
        }
    }

    // epilogue: bias + relu, direct float2 stores
    int rlo = lane >> 2;
    int cpos = (lane & 3) * 2;
#pragma unroll
    for (int mt = 0; mt < 2; mt++) {
        int gr0 = m0 + warp_m * 32 + mt * 16 + rlo;
#pragma unroll
        for (int nt = 0; nt < 8; nt++) {
            int gc = n0 + warp_n * 64 + nt * 8 + cpos;
            float2 b2 = *(const float2*)(bias + gc);
            float v0 = c[mt][nt][0] + b2.x, v1 = c[mt][nt][1] + b2.y;
            float v2 = c[mt][nt][2] + b2.x, v3 = c[mt][nt][3] + b2.y;
            if (doRelu) {
                v0 = fmaxf(v0, 0.f); v1 = fmaxf(v1, 0.f);
                v2 = fmaxf(v2, 0.f); v3 = fmaxf(v3, 0.f);
            }
            if (gr0 < M)     { float2 w = {v0, v1}; *(float2*)(C + (size_t)gr0 * HID + gc) = w; }
            if (gr0 + 8 < M) { float2 w = {v2, v3}; *(float2*)(C + (size_t)(gr0 + 8) * HID + gc) = w; }
        }
    }
}

// ---------------- aggregation ----------------
__global__ void __launch_bounds__(128)
aggregate_kernel()
{
    int d = blockIdx.x;
    int t = threadIdx.x;
    float4 acc = make_float4(0.f, 0.f, 0.f, 0.f);
    int beg = g_rowptr[d], end = g_rowptr[d + 1];
    for (int j = beg; j < end; j++) {
        int s = g_col[j];
        float4 v = *(const float4*)(g_msg + (size_t)s * HID + t * 4);
        acc.x += v.x; acc.y += v.y; acc.z += v.z; acc.w += v.w;
    }
    *(float4*)(g_aggr + (size_t)d * HID + t * 4) = acc;
}

// ---------------- output projection ----------------
__global__ void out_kernel(const float* __restrict__ Wout,
                           const float* __restrict__ bout,
                           float* __restrict__ out, int n)
{
    int warp = (blockIdx.x * blockDim.x + threadIdx.x) >> 5;
    int lane = threadIdx.x & 31;
    if (warp >= n) return;
    const float* hr = g_h + (size_t)warp * HID;
    float s = 0.f;
#pragma unroll 4
    for (int k = lane; k < HID; k += 32) s += hr[k] * Wout[k];
#pragma unroll
    for (int o = 16; o; o >>= 1) s += __shfl_down_sync(0xffffffffu, s, o);
    if (lane == 0) out[warp] = s + bout[0];
}

// ---------------- launcher ----------------
extern "C" void kernel_launch(void* const* d_in, const int* in_sizes, int n_in,
                              void* d_out, int out_size)
{
    const float* x     = (const float*)d_in[0];
    const void*  eidx  = d_in[1];
    const float* W_in  = (const float*)d_in[2];
    const float* b_in  = (const float*)d_in[3];
    const float* msg_W = (const float*)d_in[4];
    const float* msg_b = (const float*)d_in[5];
    const float* upd_W = (const float*)d_in[6];
    const float* upd_b = (const float*)d_in[7];
    const float* W_out = (const float*)d_in[8];
    const float* b_out = (const float*)d_in[9];
    float* out = (float*)d_out;

    cudaFuncSetAttribute(gemm_mma, cudaFuncAttributeMaxDynamicSharedMemorySize, GSMEM);

    // ---- dtype sniff + CSR build ----
    sniff_kernel<<<1, 256>>>((const unsigned int*)eidx);
    zero_deg_kernel<<<(NNODES + 255) / 256, 256>>>();
    hist_kernel<<<(NEDGES + 255) / 256, 256>>>(eidx, NEDGES);
    scan_kernel<<<1, 1024>>>(NNODES, NEDGES);
    fill_kernel<<<(NEDGES + 255) / 256, 256>>>(eidx, NEDGES);

    dim3 ggrid(HID / 128, (NNODES + 127) / 128);   // (4, 79)

    // ---- input embedding: h = relu(x @ W_in + b_in) ----
    conv_A<<<(NNODES * (INCH / 4) + 255) / 256, 256>>>(x, 0, 0, INCH, NNODES);
    conv_W<<<dim3(HID / 32, INCH / 32), dim3(32, 8)>>>(W_in, INCH);
    gemm_mma<<<ggrid, 256, GSMEM>>>(INCH, b_in, /*c=*/1, NNODES, 1);

    int cur = 1, nxt = 2;
    for (int l = 0; l < 2; l++) {
        const float* mW = msg_W + (size_t)l * HID * HID;
        const float* mb = msg_b + (size_t)l * HID;
        const float* uW = upd_W + (size_t)l * 2 * HID * HID;
        const float* ub = upd_b + (size_t)l * HID;

        // node-level messages (gather commutes with linear+bias+relu)
        conv_A<<<(NNODES * (HID / 4) + 255) / 256, 256>>>(nullptr, cur, 0, HID, NNODES);
        conv_W<<<dim3(HID / 32, HID / 32), dim3(32, 8)>>>(mW, HID);
        gemm_mma<<<ggrid, 256, GSMEM>>>(HID, mb, /*c=*/3, NNODES, 1);

        aggregate_kernel<<<NNODES, 128>>>();

        // update: relu([h, aggr] @ upd_W + b): aggr -> staging cols 512..1023, K=1024
        conv_A<<<(NNODES * (HID / 4) + 255) / 256, 256>>>(nullptr, 4, HID, HID, NNODES);
        conv_W<<<dim3(HID / 32, 1024 / 32), dim3(32, 8)>>>(uW, 1024);
        gemm_mma<<<ggrid, 256, GSMEM>>>(1024, ub, /*c=*/nxt, NNODES, 1);

        int t = cur; cur = nxt; nxt = t;
    }
    // after 2 layers cur == 1 (g_h)

    out_kernel<<<(NNODES * 32 + 255) / 256, 256>>>(W_out, b_out, out, NNODES);
}

// round 8
// speedup vs baseline: 2.3588x; 1.0709x over previous
#include <cuda_runtime.h>
#include <cuda_bf16.h>
#include <cstdint>

#define NNODES 10000
#define NEDGES 160000
#define INCH   256
#define HID    512
#define LDA    1024          // staging row stride (bf16 elems)

// ---------------- device scratch (referenced ONLY from device code) ----------------
// Activation staging: 2 ping-pong stages, hi/lo bf16 split. No fp32 intermediates.
__device__ __nv_bfloat16 g_ahi[2 * NNODES * LDA];
__device__ __nv_bfloat16 g_alo[2 * NNODES * LDA];
__device__ __nv_bfloat16 g_mhi[NNODES * HID];     // message staging
__device__ __nv_bfloat16 g_mlo[NNODES * HID];
__device__ __nv_bfloat16 g_whi[HID * 1024];       // transposed weights [512, K]
__device__ __nv_bfloat16 g_wlo[HID * 1024];
__device__ int   g_deg   [NNODES];
__device__ int   g_rowptr[NNODES + 1];
__device__ int   g_cursor[NNODES];
__device__ int   g_col   [NEDGES];
__device__ int   g_is64;

__device__ __forceinline__ uint32_t smem_u32(const void* p) {
    uint32_t a;
    asm("{ .reg .u64 t; cvta.to.shared.u64 t, %1; cvt.u32.u64 %0, t; }" : "=r"(a) : "l"(p));
    return a;
}
#define SWZ128(o) ((o) ^ (((o) >> 3) & 0x70))

#define LDSM4(r, addr)                                                        \
    asm volatile("ldmatrix.sync.aligned.m8n8.x4.shared.b16 {%0,%1,%2,%3}, [%4];" \
        : "=r"((r)[0]), "=r"((r)[1]), "=r"((r)[2]), "=r"((r)[3]) : "r"(addr))

#define MMA_BF16(d, a, b)                                                     \
    asm volatile("mma.sync.aligned.m16n8k16.row.col.f32.bf16.bf16.f32 "       \
        "{%0,%1,%2,%3}, {%4,%5,%6,%7}, {%8,%9}, {%0,%1,%2,%3};"               \
        : "+f"((d)[0]), "+f"((d)[1]), "+f"((d)[2]), "+f"((d)[3])              \
        : "r"((a)[0]), "r"((a)[1]), "r"((a)[2]), "r"((a)[3]),                 \
          "r"((b)[0]), "r"((b)[1]))

#define CP16(sa, gp)  asm volatile("cp.async.cg.shared.global [%0], [%1], 16;" :: "r"(sa), "l"(gp))
#define CP_COMMIT()   asm volatile("cp.async.commit_group;" ::: "memory")
#define CP_WAIT0()    asm volatile("cp.async.wait_group 0;" ::: "memory")
#define CP_WAIT1()    asm volatile("cp.async.wait_group 1;" ::: "memory")

__device__ __forceinline__ void split_bf16(float v, __nv_bfloat16& h, __nv_bfloat16& l) {
    h = __float2bfloat16_rn(v);
    l = __float2bfloat16_rn(v - __bfloat162float(h));
}

// ---------------- edge index (dtype-robust) ----------------
__device__ __forceinline__ int edge_at(const void* p, int which, int e) {
    long long v;
    if (g_is64) v = ((const long long*)p)[(size_t)which * NEDGES + e];
    else        v = ((const int*)p)[(size_t)which * NEDGES + e];
    int iv = (int)v;
    if (iv < 0) iv = 0;
    if (iv >= NNODES) iv = NNODES - 1;
    return iv;
}

__global__ void sniff_kernel(const unsigned int* __restrict__ w) {
    __shared__ int nz;
    if (threadIdx.x == 0) nz = 0;
    __syncthreads();
    int c = 0;
    for (int i = threadIdx.x; i < 2048; i += blockDim.x)
        if (w[2 * i + 1] != 0u) c++;
    if (c) atomicAdd(&nz, c);
    __syncthreads();
    if (threadIdx.x == 0) g_is64 = (nz == 0) ? 1 : 0;
}

// ---------------- CSR build ----------------
__global__ void zero_deg_kernel() {
    int i = blockIdx.x * blockDim.x + threadIdx.x;
    if (i < NNODES) g_deg[i] = 0;
}
__global__ void hist_kernel(const void* __restrict__ eidx, int nE) {
    int e = blockIdx.x * blockDim.x + threadIdx.x;
    if (e < nE) atomicAdd(&g_deg[edge_at(eidx, 1, e)], 1);
}
__global__ void scan_kernel(int n, int nE) {
    __shared__ int wsum[32];
    int tid = threadIdx.x;                 // 1024 threads
    const int CH = (n + 1023) / 1024;
    int start = tid * CH;
    int s = 0;
    for (int i = 0; i < CH; i++) {
        int idx = start + i;
        if (idx < n) s += g_deg[idx];
    }
    int lane = tid & 31, warp = tid >> 5;
    int v = s;
#pragma unroll
    for (int o = 1; o < 32; o <<= 1) {
        int t = __shfl_up_sync(0xffffffffu, v, o);
        if (lane >= o) v += t;
    }
    if (lane == 31) wsum[warp] = v;
    __syncthreads();
    if (warp == 0) {
        int w = wsum[lane];
#pragma unroll
        for (int o = 1; o < 32; o <<= 1) {
            int t = __shfl_up_sync(0xffffffffu, w, o);
            if (lane >= o) w += t;
        }
        wsum[lane] = w;
    }
    __syncthreads();
    int excl = v - s + (warp ? wsum[warp - 1] : 0);
    int run = excl;
    for (int i = 0; i < CH; i++) {
        int idx = start + i;
        if (idx < n) { g_rowptr[idx] = run; g_cursor[idx] = run; run += g_deg[idx]; }
    }
    if (tid == 1023) g_rowptr[n] = nE;
}
__global__ void fill_kernel(const void* __restrict__ eidx, int nE) {
    int e = blockIdx.x * blockDim.x + threadIdx.x;
    if (e < nE) {
        int d = edge_at(eidx, 1, e);
        int pos = atomicAdd(&g_cursor[d], 1);
        g_col[pos] = edge_at(eidx, 0, e);
    }
}

// ---------------- x -> hi/lo bf16 into stage dstage cols [0, ncols) ----------------
__global__ void conv_A(const float* __restrict__ src, int dstage, int ncols, int M) {
    int nq = ncols >> 2;
    int i = blockIdx.x * blockDim.x + threadIdx.x;
    if (i >= M * nq) return;
    int row = i / nq;
    int c = (i - row * nq) * 4;
    float4 v = *(const float4*)(src + (size_t)row * ncols + c);
    __nv_bfloat16 hx, hy, hz, hw, lx, ly, lz, lw;
    split_bf16(v.x, hx, lx); split_bf16(v.y, hy, ly);
    split_bf16(v.z, hz, lz); split_bf16(v.w, hw, lw);
    size_t o = (size_t)dstage * NNODES * LDA + (size_t)row * LDA + c;
    __nv_bfloat162* ph = (__nv_bfloat162*)(g_ahi + o);
    __nv_bfloat162* pl = (__nv_bfloat162*)(g_alo + o);
    ph[0] = __nv_bfloat162(hx, hy); ph[1] = __nv_bfloat162(hz, hw);
    pl[0] = __nv_bfloat162(lx, ly); pl[1] = __nv_bfloat162(lz, lw);
}

// W: fp32 [K, 512] -> transposed hi/lo bf16 [512, K]
__global__ void conv_W(const float* __restrict__ W, int K) {
    __shared__ float tile[32][33];
    int n0 = blockIdx.x * 32, k0 = blockIdx.y * 32;
    int tx = threadIdx.x, ty = threadIdx.y;        // (32, 8)
    for (int i = ty; i < 32; i += 8)
        tile[i][tx] = W[(size_t)(k0 + i) * HID + n0 + tx];
    __syncthreads();
    for (int i = ty; i < 32; i += 8) {
        float v = tile[tx][i];                      // = W[k0+tx][n0+i]
        __nv_bfloat16 h, l;
        split_bf16(v, h, l);
        size_t o = (size_t)(n0 + i) * K + k0 + tx;
        g_whi[o] = h; g_wlo[o] = l;
    }
}

// ---------------- mma.sync GEMM, 2-stage cp.async ----------------
// C[256x128 tile] = relu(A @ W^T + bias), written as hi/lo bf16 to staging.
// Block tile 256x128, BK=64, 256 threads (8 warps, warp tile 64x64).
// SMEM stage (96KB): Ahi 32K | Alo 32K | Bhi 16K | Blo 16K. 2 stages = 192KB.
#define STG_BYTES 98304
#define GSMEM (2 * STG_BYTES)

__device__ __forceinline__ void load_stage(
    uint32_t st, const __nv_bfloat16* __restrict__ Ah, const __nv_bfloat16* __restrict__ Al,
    int kb, int m0, int n0, int K, int M, int tid)
{
#pragma unroll
    for (int t = 0; t < 8; t++) {
        int i = tid + t * 256;
        int row = i >> 3, grp = i & 7;
        int gr = m0 + row; if (gr >= M) gr = M - 1;
        size_t off = (size_t)gr * LDA + kb * 64 + grp * 8;
        uint32_t sw = SWZ128(row * 128 + grp * 16);
        CP16(st + sw,         (const char*)(Ah + off));
        CP16(st + 32768 + sw, (const char*)(Al + off));
    }
#pragma unroll
    for (int t = 0; t < 4; t++) {
        int i = tid + t * 256;
        int row = i >> 3, grp = i & 7;
        size_t off = (size_t)(n0 + row) * K + kb * 64 + grp * 8;
        uint32_t sw = SWZ128(row * 128 + grp * 16);
        CP16(st + 65536 + sw, (const char*)(g_whi + off));
        CP16(st + 81920 + sw, (const char*)(g_wlo + off));
    }
}

__global__ void __launch_bounds__(256, 1)
gemm_mma(int asel, int K, const float* __restrict__ bias, int dsel, int M, int doRelu)
{
    extern __shared__ char smem[];
    uint32_t sb = smem_u32(smem);
    const __nv_bfloat16* Ah = g_ahi + (size_t)asel * NNODES * LDA;
    const __nv_bfloat16* Al = g_alo + (size_t)asel * NNODES * LDA;
    __nv_bfloat16 *Dh, *Dl;
    int dstride;
    if (dsel == 2) { Dh = g_mhi; Dl = g_mlo; dstride = HID; }
    else { Dh = g_ahi + (size_t)dsel * NNODES * LDA; Dl = g_alo + (size_t)dsel * NNODES * LDA; dstride = LDA; }

    int tid = threadIdx.x, lane = tid & 31, wid = tid >> 5;
    int warp_m = wid & 3, warp_n = wid >> 2;      // 4 x 2 warps -> 256 x 128
    int m0 = blockIdx.y * 256, n0 = blockIdx.x * 128;

    float c[4][8][4];
#pragma unroll
    for (int mt = 0; mt < 4; mt++)
#pragma unroll
        for (int nt = 0; nt < 8; nt++)
#pragma unroll
            for (int j = 0; j < 4; j++) c[mt][nt][j] = 0.f;

    const int q = lane >> 3, li = lane & 7;
    int NKB = K >> 6;

    load_stage(sb, Ah, Al, 0, m0, n0, K, M, tid);
    CP_COMMIT();

    for (int kb = 0; kb < NKB; kb++) {
        if (kb + 1 < NKB) {
            load_stage(sb + ((kb + 1) & 1) * STG_BYTES, Ah, Al, kb + 1, m0, n0, K, M, tid);
            CP_COMMIT();
            CP_WAIT1();
        } else {
            CP_WAIT0();
        }
        __syncthreads();

        uint32_t st = sb + (kb & 1) * STG_BYTES;
#pragma unroll
        for (int s = 0; s < 4; s++) {
            uint32_t ah[4][4], al[4][4], bh[8][2], bl[8][2];
#pragma unroll
            for (int mt = 0; mt < 4; mt++) {
                int row = warp_m * 64 + mt * 16 + ((q & 1) << 3) + li;
                int grp = s * 2 + (q >> 1);
                uint32_t ad = st + SWZ128(row * 128 + grp * 16);
                LDSM4(ah[mt], ad);
                LDSM4(al[mt], ad + 32768);
            }
#pragma unroll
            for (int np = 0; np < 4; np++) {
                int nrow = warp_n * 64 + np * 16 + ((q >> 1) << 3) + li;
                int grp = s * 2 + (q & 1);
                uint32_t bd = st + 65536 + SWZ128(nrow * 128 + grp * 16);
                uint32_t r[4];
                LDSM4(r, bd);
                bh[np*2][0] = r[0]; bh[np*2][1] = r[1];
                bh[np*2+1][0] = r[2]; bh[np*2+1][1] = r[3];
                LDSM4(r, bd + 16384);
                bl[np*2][0] = r[0]; bl[np*2][1] = r[1];
                bl[np*2+1][0] = r[2]; bl[np*2+1][1] = r[3];
            }
#pragma unroll
            for (int mt = 0; mt < 4; mt++)
#pragma unroll
                for (int nt = 0; nt < 8; nt++) {
                    MMA_BF16(c[mt][nt], ah[mt], bh[nt]);
                    MMA_BF16(c[mt][nt], ah[mt], bl[nt]);
                    MMA_BF16(c[mt][nt], al[mt], bh[nt]);
                }
        }
        __syncthreads();
    }

    // epilogue: bias + relu + hi/lo bf16 split, direct stores to staging
    int rlo = lane >> 2;
    int cpos = (lane & 3) * 2;
#pragma unroll
    for (int mt = 0; mt < 4; mt++) {
        int r0 = m0 + warp_m * 64 + mt * 16 + rlo;
#pragma unroll
        for (int nt = 0; nt < 8; nt++) {
            int gc = n0 + warp_n * 64 + nt * 8 + cpos;
            float2 b2 = *(const float2*)(bias + gc);
            float v0 = c[mt][nt][0] + b2.x, v1 = c[mt][nt][1] + b2.y;
            float v2 = c[mt][nt][2] + b2.x, v3 = c[mt][nt][3] + b2.y;
            if (doRelu) {
                v0 = fmaxf(v0, 0.f); v1 = fmaxf(v1, 0.f);
                v2 = fmaxf(v2, 0.f); v3 = fmaxf(v3, 0.f);
            }
            __nv_bfloat16 h0, l0, h1, l1;
            if (r0 < M) {
                split_bf16(v0, h0, l0); split_bf16(v1, h1, l1);
                *(__nv_bfloat162*)(Dh + (size_t)r0 * dstride + gc) = __nv_bfloat162(h0, h1);
                *(__nv_bfloat162*)(Dl + (size_t)r0 * dstride + gc) = __nv_bfloat162(l0, l1);
            }
            if (r0 + 8 < M) {
                split_bf16(v2, h0, l0); split_bf16(v3, h1, l1);
                *(__nv_bfloat162*)(Dh + (size_t)(r0 + 8) * dstride + gc) = __nv_bfloat162(h0, h1);
                *(__nv_bfloat162*)(Dl + (size_t)(r0 + 8) * dstride + gc) = __nv_bfloat162(l0, l1);
            }
        }
    }
}

// ---------------- aggregation: stage[cur] cols 512..1023 = sum of msg rows ----------------
__global__ void __launch_bounds__(128)
aggregate_kernel(int cur)
{
    int d = blockIdx.x;
    int t = threadIdx.x;                 // 128 threads x 4 channels
    int c = t * 4;
    float a0 = 0.f, a1 = 0.f, a2 = 0.f, a3 = 0.f;
    int beg = g_rowptr[d], end = g_rowptr[d + 1];
    for (int j = beg; j < end; j++) {
        int s = g_col[j];
        const __nv_bfloat162* ph = (const __nv_bfloat162*)(g_mhi + (size_t)s * HID + c);
        const __nv_bfloat162* pl = (const __nv_bfloat162*)(g_mlo + (size_t)s * HID + c);
        __nv_bfloat162 h0 = ph[0], h1 = ph[1], l0 = pl[0], l1 = pl[1];
        a0 += __bfloat162float(h0.x) + __bfloat162float(l0.x);
        a1 += __bfloat162float(h0.y) + __bfloat162float(l0.y);
        a2 += __bfloat162float(h1.x) + __bfloat162float(l1.x);
        a3 += __bfloat162float(h1.y) + __bfloat162float(l1.y);
    }
    __nv_bfloat16 h0, l0, h1, l1, h2, l2, h3, l3;
    split_bf16(a0, h0, l0); split_bf16(a1, h1, l1);
    split_bf16(a2, h2, l2); split_bf16(a3, h3, l3);
    size_t o = (size_t)cur * NNODES * LDA + (size_t)d * LDA + 512 + c;
    __nv_bfloat162* ph = (__nv_bfloat162*)(g_ahi + o);
    __nv_bfloat162* pl = (__nv_bfloat162*)(g_alo + o);
    ph[0] = __nv_bfloat162(h0, h1); ph[1] = __nv_bfloat162(h2, h3);
    pl[0] = __nv_bfloat162(l0, l1); pl[1] = __nv_bfloat162(l2, l3);
}

// ---------------- output projection: out[i] = (hi+lo)[i,:] . W_out + b_out ----------------
__global__ void out_kernel(const float* __restrict__ Wout,
                           const float* __restrict__ bout,
                           float* __restrict__ out, int n, int hsel)
{
    int warp = (blockIdx.x * blockDim.x + threadIdx.x) >> 5;
    int lane = threadIdx.x & 31;
    if (warp >= n) return;
    const __nv_bfloat16* hh = g_ahi + (size_t)hsel * NNODES * LDA + (size_t)warp * LDA;
    const __nv_bfloat16* hl = g_alo + (size_t)hsel * NNODES * LDA + (size_t)warp * LDA;
    float s = 0.f;
#pragma unroll 4
    for (int k = lane; k < HID; k += 32)
        s += (__bfloat162float(hh[k]) + __bfloat162float(hl[k])) * Wout[k];
#pragma unroll
    for (int o = 16; o; o >>= 1) s += __shfl_down_sync(0xffffffffu, s, o);
    if (lane == 0) out[warp] = s + bout[0];
}

// ---------------- launcher ----------------
extern "C" void kernel_launch(void* const* d_in, const int* in_sizes, int n_in,
                              void* d_out, int out_size)
{
    const float* x     = (const float*)d_in[0];
    const void*  eidx  = d_in[1];
    const float* W_in  = (const float*)d_in[2];
    const float* b_in  = (const float*)d_in[3];
    const float* msg_W = (const float*)d_in[4];
    const float* msg_b = (const float*)d_in[5];
    const float* upd_W = (const float*)d_in[6];
    const float* upd_b = (const float*)d_in[7];
    const float* W_out = (const float*)d_in[8];
    const float* b_out = (const float*)d_in[9];
    float* out = (float*)d_out;

    cudaFuncSetAttribute(gemm_mma, cudaFuncAttributeMaxDynamicSharedMemorySize, GSMEM);

    // ---- dtype sniff + CSR build ----
    sniff_kernel<<<1, 256>>>((const unsigned int*)eidx);
    zero_deg_kernel<<<(NNODES + 255) / 256, 256>>>();
    hist_kernel<<<(NEDGES + 255) / 256, 256>>>(eidx, NEDGES);
    scan_kernel<<<1, 1024>>>(NNODES, NEDGES);
    fill_kernel<<<(NEDGES + 255) / 256, 256>>>(eidx, NEDGES);

    dim3 ggrid(HID / 128, (NNODES + 255) / 256);   // (4, 40)

    // ---- input embedding: stage0 = relu(x @ W_in + b_in);  x staged in stage1 ----
    conv_A<<<(NNODES * (INCH / 4) + 255) / 256, 256>>>(x, 1, INCH, NNODES);
    conv_W<<<dim3(HID / 32, INCH / 32), dim3(32, 8)>>>(W_in, INCH);
    gemm_mma<<<ggrid, 256, GSMEM>>>(/*a=*/1, INCH, b_in, /*d=*/0, NNODES, 1);

    int cur = 0, nxt = 1;
    for (int l = 0; l < 2; l++) {
        const float* mW = msg_W + (size_t)l * HID * HID;
        const float* mb = msg_b + (size_t)l * HID;
        const float* uW = upd_W + (size_t)l * 2 * HID * HID;
        const float* ub = upd_b + (size_t)l * HID;

        // node-level messages (gather commutes with linear+bias+relu) -> msg staging
        conv_W<<<dim3(HID / 32, HID / 32), dim3(32, 8)>>>(mW, HID);
        gemm_mma<<<ggrid, 256, GSMEM>>>(cur, HID, mb, /*d=*/2, NNODES, 1);

        // scatter-add over destinations -> stage[cur] cols 512..1023
        aggregate_kernel<<<NNODES, 128>>>(cur);

        // update: relu([h, aggr] @ upd_W + b) as K=1024 GEMM -> stage[nxt] cols 0..511
        conv_W<<<dim3(HID / 32, 1024 / 32), dim3(32, 8)>>>(uW, 1024);
        gemm_mma<<<ggrid, 256, GSMEM>>>(cur, 1024, ub, nxt, NNODES, 1);

        int t = cur; cur = nxt; nxt = t;
    }
    // after 2 layers cur == 0 (stage0 holds final h)

    out_kernel<<<(NNODES * 32 + 255) / 256, 256>>>(W_out, b_out, out, NNODES, cur);
}

// round 9
// speedup vs baseline: 3.5933x; 1.5233x over previous
#include <cuda_runtime.h>
#include <cuda_fp16.h>
#include <cstdint>

#define NNODES 10000
#define NEDGES 160000
#define INCH   256
#define HID    512
#define LDA    1024          // staging row stride (fp16 elems)

// ---------------- device scratch (referenced ONLY from device code) ----------------
// Activations: single fp16, 2 ping-pong stages. Weights: fp16 hi/lo split, transposed [N,K].
__device__ __half g_act[2 * NNODES * LDA];
__device__ __half g_m  [NNODES * HID];          // message staging
__device__ __half g_wh [HID * 1024];
__device__ __half g_wl [HID * 1024];
__device__ int   g_deg   [NNODES];
__device__ int   g_rowptr[NNODES + 1];
__device__ int   g_cursor[NNODES];
__device__ int   g_col   [NEDGES];
__device__ int   g_is64;

__device__ __forceinline__ uint32_t smem_u32(const void* p) {
    uint32_t a;
    asm("{ .reg .u64 t; cvta.to.shared.u64 t, %1; cvt.u32.u64 %0, t; }" : "=r"(a) : "l"(p));
    return a;
}
#define SWZ128(o) ((o) ^ (((o) >> 3) & 0x70))

#define LDSM4(r, addr)                                                        \
    asm volatile("ldmatrix.sync.aligned.m8n8.x4.shared.b16 {%0,%1,%2,%3}, [%4];" \
        : "=r"((r)[0]), "=r"((r)[1]), "=r"((r)[2]), "=r"((r)[3]) : "r"(addr))

#define MMA_F16(d, a, b)                                                      \
    asm volatile("mma.sync.aligned.m16n8k16.row.col.f32.f16.f16.f32 "         \
        "{%0,%1,%2,%3}, {%4,%5,%6,%7}, {%8,%9}, {%0,%1,%2,%3};"               \
        : "+f"((d)[0]), "+f"((d)[1]), "+f"((d)[2]), "+f"((d)[3])              \
        : "r"((a)[0]), "r"((a)[1]), "r"((a)[2]), "r"((a)[3]),                 \
          "r"((b)[0]), "r"((b)[1]))

#define CP16(sa, gp)  asm volatile("cp.async.cg.shared.global [%0], [%1], 16;" :: "r"(sa), "l"(gp))
#define CP_COMMIT()   asm volatile("cp.async.commit_group;" ::: "memory")
#define CP_WAIT0()    asm volatile("cp.async.wait_group 0;" ::: "memory")
#define CP_WAIT1()    asm volatile("cp.async.wait_group 1;" ::: "memory")

// ---------------- edge index (dtype-robust) ----------------
__device__ __forceinline__ int edge_at(const void* p, int which, int e) {
    long long v;
    if (g_is64) v = ((const long long*)p)[(size_t)which * NEDGES + e];
    else        v = ((const int*)p)[(size_t)which * NEDGES + e];
    int iv = (int)v;
    if (iv < 0) iv = 0;
    if (iv >= NNODES) iv = NNODES - 1;
    return iv;
}

__global__ void sniff_kernel(const unsigned int* __restrict__ w) {
    __shared__ int nz;
    if (threadIdx.x == 0) nz = 0;
    __syncthreads();
    int c = 0;
    for (int i = threadIdx.x; i < 2048; i += blockDim.x)
        if (w[2 * i + 1] != 0u) c++;
    if (c) atomicAdd(&nz, c);
    __syncthreads();
    if (threadIdx.x == 0) g_is64 = (nz == 0) ? 1 : 0;
}

// ---------------- CSR build ----------------
__global__ void zero_deg_kernel() {
    int i = blockIdx.x * blockDim.x + threadIdx.x;
    if (i < NNODES) g_deg[i] = 0;
}
__global__ void hist_kernel(const void* __restrict__ eidx, int nE) {
    int e = blockIdx.x * blockDim.x + threadIdx.x;
    if (e < nE) atomicAdd(&g_deg[edge_at(eidx, 1, e)], 1);
}
__global__ void scan_kernel(int n, int nE) {
    __shared__ int wsum[32];
    int tid = threadIdx.x;                 // 1024 threads
    const int CH = (n + 1023) / 1024;
    int start = tid * CH;
    int s = 0;
    for (int i = 0; i < CH; i++) {
        int idx = start + i;
        if (idx < n) s += g_deg[idx];
    }
    int lane = tid & 31, warp = tid >> 5;
    int v = s;
#pragma unroll
    for (int o = 1; o < 32; o <<= 1) {
        int t = __shfl_up_sync(0xffffffffu, v, o);
        if (lane >= o) v += t;
    }
    if (lane == 31) wsum[warp] = v;
    __syncthreads();
    if (warp == 0) {
        int w = wsum[lane];
#pragma unroll
        for (int o = 1; o < 32; o <<= 1) {
            int t = __shfl_up_sync(0xffffffffu, w, o);
            if (lane >= o) w += t;
        }
        wsum[lane] = w;
    }
    __syncthreads();
    int excl = v - s + (warp ? wsum[warp - 1] : 0);
    int run = excl;
    for (int i = 0; i < CH; i++) {
        int idx = start + i;
        if (idx < n) { g_rowptr[idx] = run; g_cursor[idx] = run; run += g_deg[idx]; }
    }
    if (tid == 1023) g_rowptr[n] = nE;
}
__global__ void fill_kernel(const void* __restrict__ eidx, int nE) {
    int e = blockIdx.x * blockDim.x + threadIdx.x;
    if (e < nE) {
        int d = edge_at(eidx, 1, e);
        int pos = atomicAdd(&g_cursor[d], 1);
        g_col[pos] = edge_at(eidx, 0, e);
    }
}

// ---------------- x fp32 -> fp16 into stage dstage cols [0, ncols) ----------------
__global__ void conv_A(const float* __restrict__ src, int dstage, int ncols, int M) {
    int nq = ncols >> 2;
    int i = blockIdx.x * blockDim.x + threadIdx.x;
    if (i >= M * nq) return;
    int row = i / nq;
    int c = (i - row * nq) * 4;
    float4 v = *(const float4*)(src + (size_t)row * ncols + c);
    size_t o = (size_t)dstage * NNODES * LDA + (size_t)row * LDA + c;
    __half2* p = (__half2*)(g_act + o);
    p[0] = __floats2half2_rn(v.x, v.y);
    p[1] = __floats2half2_rn(v.z, v.w);
}

// W: fp32 [K, 512] -> transposed hi/lo fp16 [512, K]
__global__ void conv_W(const float* __restrict__ W, int K) {
    __shared__ float tile[32][33];
    int n0 = blockIdx.x * 32, k0 = blockIdx.y * 32;
    int tx = threadIdx.x, ty = threadIdx.y;        // (32, 8)
    for (int i = ty; i < 32; i += 8)
        tile[i][tx] = W[(size_t)(k0 + i) * HID + n0 + tx];
    __syncthreads();
    for (int i = ty; i < 32; i += 8) {
        float v = tile[tx][i];                      // = W[k0+tx][n0+i]
        __half h = __float2half_rn(v);
        __half l = __float2half_rn(v - __half2float(h));
        size_t o = (size_t)(n0 + i) * K + k0 + tx;
        g_wh[o] = h; g_wl[o] = l;
    }
}

// ---------------- mma.sync GEMM, fp16 2-pass (A single, W hi+lo), 2-stage cp.async ----------------
// Block tile 256x128, BK=64, 256 threads (8 warps, warp tile 64x64).
// SMEM stage (64KB): A 32K | Wh 16K | Wl 16K. 2 stages = 128KB.
#define STG_BYTES 65536
#define GSMEM (2 * STG_BYTES)

__device__ __forceinline__ void load_stage(
    uint32_t st, const __half* __restrict__ A,
    int kb, int m0, int n0, int K, int M, int tid)
{
#pragma unroll
    for (int t = 0; t < 8; t++) {
        int i = tid + t * 256;
        int row = i >> 3, grp = i & 7;
        int gr = m0 + row; if (gr >= M) gr = M - 1;
        size_t off = (size_t)gr * LDA + kb * 64 + grp * 8;
        uint32_t sw = SWZ128(row * 128 + grp * 16);
        CP16(st + sw, (const char*)(A + off));
    }
#pragma unroll
    for (int t = 0; t < 4; t++) {
        int i = tid + t * 256;
        int row = i >> 3, grp = i & 7;
        size_t off = (size_t)(n0 + row) * K + kb * 64 + grp * 8;
        uint32_t sw = SWZ128(row * 128 + grp * 16);
        CP16(st + 32768 + sw, (const char*)(g_wh + off));
        CP16(st + 49152 + sw, (const char*)(g_wl + off));
    }
}

__global__ void __launch_bounds__(256, 1)
gemm_mma(int asel, int K, const float* __restrict__ bias, int dsel, int M, int doRelu)
{
    extern __shared__ char smem[];
    uint32_t sb = smem_u32(smem);
    const __half* A = g_act + (size_t)asel * NNODES * LDA;
    __half* D;
    int dstride;
    if (dsel == 2) { D = g_m; dstride = HID; }
    else { D = g_act + (size_t)dsel * NNODES * LDA; dstride = LDA; }

    int tid = threadIdx.x, lane = tid & 31, wid = tid >> 5;
    int warp_m = wid & 3, warp_n = wid >> 2;      // 4 x 2 warps -> 256 x 128
    int m0 = blockIdx.y * 256, n0 = blockIdx.x * 128;

    float c[4][8][4];
#pragma unroll
    for (int mt = 0; mt < 4; mt++)
#pragma unroll
        for (int nt = 0; nt < 8; nt++)
#pragma unroll
            for (int j = 0; j < 4; j++) c[mt][nt][j] = 0.f;

    const int q = lane >> 3, li = lane & 7;
    int NKB = K >> 6;

    load_stage(sb, A, 0, m0, n0, K, M, tid);
    CP_COMMIT();

    for (int kb = 0; kb < NKB; kb++) {
        if (kb + 1 < NKB) {
            load_stage(sb + ((kb + 1) & 1) * STG_BYTES, A, kb + 1, m0, n0, K, M, tid);
            CP_COMMIT();
            CP_WAIT1();
        } else {
            CP_WAIT0();
        }
        __syncthreads();

        uint32_t st = sb + (kb & 1) * STG_BYTES;
#pragma unroll
        for (int s = 0; s < 4; s++) {
            uint32_t a[4][4], bh[8][2], bl[8][2];
#pragma unroll
            for (int mt = 0; mt < 4; mt++) {
                int row = warp_m * 64 + mt * 16 + ((q & 1) << 3) + li;
                int grp = s * 2 + (q >> 1);
                LDSM4(a[mt], st + SWZ128(row * 128 + grp * 16));
            }
#pragma unroll
            for (int np = 0; np < 4; np++) {
                int nrow = warp_n * 64 + np * 16 + ((q >> 1) << 3) + li;
                int grp = s * 2 + (q & 1);
                uint32_t bd = st + 32768 + SWZ128(nrow * 128 + grp * 16);
                uint32_t r[4];
                LDSM4(r, bd);
                bh[np*2][0] = r[0]; bh[np*2][1] = r[1];
                bh[np*2+1][0] = r[2]; bh[np*2+1][1] = r[3];
                LDSM4(r, bd + 16384);
                bl[np*2][0] = r[0]; bl[np*2][1] = r[1];
                bl[np*2+1][0] = r[2]; bl[np*2+1][1] = r[3];
            }
#pragma unroll
            for (int mt = 0; mt < 4; mt++)
#pragma unroll
                for (int nt = 0; nt < 8; nt++) {
                    MMA_F16(c[mt][nt], a[mt], bh[nt]);
                    MMA_F16(c[mt][nt], a[mt], bl[nt]);
                }
        }
        __syncthreads();
    }

    // epilogue: bias + relu, fp16 stores to staging
    int rlo = lane >> 2;
    int cpos = (lane & 3) * 2;
#pragma unroll
    for (int mt = 0; mt < 4; mt++) {
        int r0 = m0 + warp_m * 64 + mt * 16 + rlo;
#pragma unroll
        for (int nt = 0; nt < 8; nt++) {
            int gc = n0 + warp_n * 64 + nt * 8 + cpos;
            float2 b2 = *(const float2*)(bias + gc);
            float v0 = c[mt][nt][0] + b2.x, v1 = c[mt][nt][1] + b2.y;
            float v2 = c[mt][nt][2] + b2.x, v3 = c[mt][nt][3] + b2.y;
            if (doRelu) {
                v0 = fmaxf(v0, 0.f); v1 = fmaxf(v1, 0.f);
                v2 = fmaxf(v2, 0.f); v3 = fmaxf(v3, 0.f);
            }
            if (r0 < M)
                *(__half2*)(D + (size_t)r0 * dstride + gc) = __floats2half2_rn(v0, v1);
            if (r0 + 8 < M)
                *(__half2*)(D + (size_t)(r0 + 8) * dstride + gc) = __floats2half2_rn(v2, v3);
        }
    }
}

// ---------------- aggregation: stage[cur] cols 512..1023 = sum of msg rows ----------------
__global__ void __launch_bounds__(128)
aggregate_kernel(int cur)
{
    int d = blockIdx.x;
    int t = threadIdx.x;                 // 128 threads x 4 channels
    int c = t * 4;
    float a0 = 0.f, a1 = 0.f, a2 = 0.f, a3 = 0.f;
    int beg = g_rowptr[d], end = g_rowptr[d + 1];
    for (int j = beg; j < end; j++) {
        int s = g_col[j];
        const __half2* p = (const __half2*)(g_m + (size_t)s * HID + c);
        __half2 u0 = p[0], u1 = p[1];
        float2 f0 = __half22float2(u0), f1 = __half22float2(u1);
        a0 += f0.x; a1 += f0.y; a2 += f1.x; a3 += f1.y;
    }
    size_t o = (size_t)cur * NNODES * LDA + (size_t)d * LDA + 512 + c;
    __half2* p = (__half2*)(g_act + o);
    p[0] = __floats2half2_rn(a0, a1);
    p[1] = __floats2half2_rn(a2, a3);
}

// ---------------- output projection: out[i] = h[i,:] . W_out + b_out ----------------
__global__ void out_kernel(const float* __restrict__ Wout,
                           const float* __restrict__ bout,
                           float* __restrict__ out, int n, int hsel)
{
    int warp = (blockIdx.x * blockDim.x + threadIdx.x) >> 5;
    int lane = threadIdx.x & 31;
    if (warp >= n) return;
    const __half* hr = g_act + (size_t)hsel * NNODES * LDA + (size_t)warp * LDA;
    float s = 0.f;
#pragma unroll 4
    for (int k = lane; k < HID; k += 32)
        s += __half2float(hr[k]) * Wout[k];
#pragma unroll
    for (int o = 16; o; o >>= 1) s += __shfl_down_sync(0xffffffffu, s, o);
    if (lane == 0) out[warp] = s + bout[0];
}

// ---------------- launcher ----------------
extern "C" void kernel_launch(void* const* d_in, const int* in_sizes, int n_in,
                              void* d_out, int out_size)
{
    const float* x     = (const float*)d_in[0];
    const void*  eidx  = d_in[1];
    const float* W_in  = (const float*)d_in[2];
    const float* b_in  = (const float*)d_in[3];
    const float* msg_W = (const float*)d_in[4];
    const float* msg_b = (const float*)d_in[5];
    const float* upd_W = (const float*)d_in[6];
    const float* upd_b = (const float*)d_in[7];
    const float* W_out = (const float*)d_in[8];
    const float* b_out = (const float*)d_in[9];
    float* out = (float*)d_out;

    cudaFuncSetAttribute(gemm_mma, cudaFuncAttributeMaxDynamicSharedMemorySize, GSMEM);

    // ---- dtype sniff + CSR build ----
    sniff_kernel<<<1, 256>>>((const unsigned int*)eidx);
    zero_deg_kernel<<<(NNODES + 255) / 256, 256>>>();
    hist_kernel<<<(NEDGES + 255) / 256, 256>>>(eidx, NEDGES);
    scan_kernel<<<1, 1024>>>(NNODES, NEDGES);
    fill_kernel<<<(NEDGES + 255) / 256, 256>>>(eidx, NEDGES);

    dim3 ggrid(HID / 128, (NNODES + 255) / 256);   // (4, 40)

    // ---- input embedding: stage0 = relu(x @ W_in + b_in);  x staged in stage1 ----
    conv_A<<<(NNODES * (INCH / 4) + 255) / 256, 256>>>(x, 1, INCH, NNODES);
    conv_W<<<dim3(HID / 32, INCH / 32), dim3(32, 8)>>>(W_in, INCH);
    gemm_mma<<<ggrid, 256, GSMEM>>>(/*a=*/1, INCH, b_in, /*d=*/0, NNODES, 1);

    int cur = 0, nxt = 1;
    for (int l = 0; l < 2; l++) {
        const float* mW = msg_W + (size_t)l * HID * HID;
        const float* mb = msg_b + (size_t)l * HID;
        const float* uW = upd_W + (size_t)l * 2 * HID * HID;
        const float* ub = upd_b + (size_t)l * HID;

        // node-level messages (gather commutes with linear+bias+relu) -> msg staging
        conv_W<<<dim3(HID / 32, HID / 32), dim3(32, 8)>>>(mW, HID);
        gemm_mma<<<ggrid, 256, GSMEM>>>(cur, HID, mb, /*d=*/2, NNODES, 1);

        // scatter-add over destinations -> stage[cur] cols 512..1023
        aggregate_kernel<<<NNODES, 128>>>(cur);

        // update: relu([h, aggr] @ upd_W + b) as K=1024 GEMM -> stage[nxt] cols 0..511
        conv_W<<<dim3(HID / 32, 1024 / 32), dim3(32, 8)>>>(uW, 1024);
        gemm_mma<<<ggrid, 256, GSMEM>>>(cur, 1024, ub, nxt, NNODES, 1);

        int t = cur; cur = nxt; nxt = t;
    }
    // after 2 layers cur == 0 (stage0 holds final h)

    out_kernel<<<(NNODES * 32 + 255) / 256, 256>>>(W_out, b_out, out, NNODES, cur);
}

// round 13
// speedup vs baseline: 5.2858x; 1.4710x over previous
#include <cuda_runtime.h>
#include <cuda_fp16.h>
#include <cstdint>

#define NNODES 10000
#define NEDGES 160000
#define INCH   256
#define HID    512
#define LDA    1024          // activation staging row stride (fp16 elems)

// weight region offsets within g_wh/g_wl (elems): [N=512, K] transposed per GEMM
#define WOFF_IN   0
#define WOFF_MSG0 (256 * 512)
#define WOFF_UPD0 (WOFF_MSG0 + 512 * 512)
#define WOFF_MSG1 (WOFF_UPD0 + 1024 * 512)
#define WOFF_UPD1 (WOFF_MSG1 + 512 * 512)
#define WTOTAL    (WOFF_UPD1 + 1024 * 512)

// ---------------- device scratch (referenced ONLY from device code) ----------------
__device__ __half g_act[2 * NNODES * LDA];
__device__ __half g_m  [NNODES * HID];
__device__ __half g_wh [WTOTAL];
__device__ __half g_wl [WTOTAL];
__device__ int   g_deg   [NNODES];
__device__ int   g_rowptr[NNODES + 1];
__device__ int   g_cursor[NNODES];
__device__ int   g_col   [NEDGES];
__device__ int   g_is64;

__device__ __forceinline__ uint32_t smem_u32(const void* p) {
    uint32_t a;
    asm("{ .reg .u64 t; cvta.to.shared.u64 t, %1; cvt.u32.u64 %0, t; }" : "=r"(a) : "l"(p));
    return a;
}
#define SWZ128(o) ((o) ^ (((o) >> 3) & 0x70))

#define LDSM4(r, addr)                                                        \
    asm volatile("ldmatrix.sync.aligned.m8n8.x4.shared.b16 {%0,%1,%2,%3}, [%4];" \
        : "=r"((r)[0]), "=r"((r)[1]), "=r"((r)[2]), "=r"((r)[3]) : "r"(addr))

#define MMA_F16(d, a, b)                                                      \
    asm volatile("mma.sync.aligned.m16n8k16.row.col.f32.f16.f16.f32 "         \
        "{%0,%1,%2,%3}, {%4,%5,%6,%7}, {%8,%9}, {%0,%1,%2,%3};"               \
        : "+f"((d)[0]), "+f"((d)[1]), "+f"((d)[2]), "+f"((d)[3])              \
        : "r"((a)[0]), "r"((a)[1]), "r"((a)[2]), "r"((a)[3]),                 \
          "r"((b)[0]), "r"((b)[1]))

#define CP16(sa, gp)  asm volatile("cp.async.cg.shared.global [%0], [%1], 16;" :: "r"(sa), "l"(gp))
#define CP_COMMIT()   asm volatile("cp.async.commit_group;" ::: "memory")
#define CP_WAIT0()    asm volatile("cp.async.wait_group 0;" ::: "memory")
#define CP_WAIT1()    asm volatile("cp.async.wait_group 1;" ::: "memory")

// ---------------- edge index (dtype-robust) ----------------
__device__ __forceinline__ int edge_at(const void* p, int which, int e) {
    long long v;
    if (g_is64) v = ((const long long*)p)[(size_t)which * NEDGES + e];
    else        v = ((const int*)p)[(size_t)which * NEDGES + e];
    int iv = (int)v;
    if (iv < 0) iv = 0;
    if (iv >= NNODES) iv = NNODES - 1;
    return iv;
}

__global__ void sniff_kernel(const unsigned int* __restrict__ w) {
    __shared__ int nz;
    if (threadIdx.x == 0) nz = 0;
    __syncthreads();
    int c = 0;
    for (int i = threadIdx.x; i < 2048; i += blockDim.x)
        if (w[2 * i + 1] != 0u) c++;
    if (c) atomicAdd(&nz, c);
    __syncthreads();
    if (threadIdx.x == 0) g_is64 = (nz == 0) ? 1 : 0;
}

// ---------------- CSR build ----------------
__global__ void zero_deg_kernel() {
    int i = blockIdx.x * blockDim.x + threadIdx.x;
    if (i < NNODES) g_deg[i] = 0;
}
__global__ void hist_kernel(const void* __restrict__ eidx, int nE) {
    int e = blockIdx.x * blockDim.x + threadIdx.x;
    if (e < nE) atomicAdd(&g_deg[edge_at(eidx, 1, e)], 1);
}
__global__ void scan_kernel(int n, int nE) {
    __shared__ int wsum[32];
    int tid = threadIdx.x;                 // 1024 threads
    const int CH = (n + 1023) / 1024;
    int start = tid * CH;
    int s = 0;
    for (int i = 0; i < CH; i++) {
        int idx = start + i;
        if (idx < n) s += g_deg[idx];
    }
    int lane = tid & 31, warp = tid >> 5;
    int v = s;
#pragma unroll
    for (int o = 1; o < 32; o <<= 1) {
        int t = __shfl_up_sync(0xffffffffu, v, o);
        if (lane >= o) v += t;
    }
    if (lane == 31) wsum[warp] = v;
    __syncthreads();
    if (warp == 0) {
        int w = wsum[lane];
#pragma unroll
        for (int o = 1; o < 32; o <<= 1) {
            int t = __shfl_up_sync(0xffffffffu, w, o);
            if (lane >= o) w += t;
        }
        wsum[lane] = w;
    }
    __syncthreads();
    int excl = v - s + (warp ? wsum[warp - 1] : 0);
    int run = excl;
    for (int i = 0; i < CH; i++) {
        int idx = start + i;
        if (idx < n) { g_rowptr[idx] = run; g_cursor[idx] = run; run += g_deg[idx]; }
    }
    if (tid == 1023) g_rowptr[n] = nE;
}
__global__ void fill_kernel(const void* __restrict__ eidx, int nE) {
    int e = blockIdx.x * blockDim.x + threadIdx.x;
    if (e < nE) {
        int d = edge_at(eidx, 1, e);
        int pos = atomicAdd(&g_cursor[d], 1);
        g_col[pos] = edge_at(eidx, 0, e);
    }
}

// ---------------- x fp32 -> fp16 into stage dstage cols [0, ncols) ----------------
__global__ void conv_A(const float* __restrict__ src, int dstage, int ncols, int M) {
    int nq = ncols >> 2;
    int i = blockIdx.x * blockDim.x + threadIdx.x;
    if (i >= M * nq) return;
    int row = i / nq;
    int c = (i - row * nq) * 4;
    float4 v = *(const float4*)(src + (size_t)row * ncols + c);
    size_t o = (size_t)dstage * NNODES * LDA + (size_t)row * LDA + c;
    __half2* p = (__half2*)(g_act + o);
    p[0] = __floats2half2_rn(v.x, v.y);
    p[1] = __floats2half2_rn(v.z, v.w);
}

// W: fp32 [K, 512] -> transposed hi/lo fp16 [512, K] at region offset woff
__global__ void conv_W(const float* __restrict__ W, int K, int woff) {
    __shared__ float tile[32][33];
    int n0 = blockIdx.x * 32, k0 = blockIdx.y * 32;
    int tx = threadIdx.x, ty = threadIdx.y;        // (32, 8)
    for (int i = ty; i < 32; i += 8)
        tile[i][tx] = W[(size_t)(k0 + i) * HID + n0 + tx];
    __syncthreads();
    for (int i = ty; i < 32; i += 8) {
        float v = tile[tx][i];                      // = W[k0+tx][n0+i]
        __half h = __float2half_rn(v);
        __half l = __float2half_rn(v - __half2float(h));
        size_t o = (size_t)woff + (size_t)(n0 + i) * K + k0 + tx;
        g_wh[o] = h; g_wl[o] = l;
    }
}

// ---------------- mma.sync GEMM, fp16 2-pass, 2-stage cp.async ----------------
// Block tile 160x256, BK=64, 256 threads (8 warps, warp tile 80x64).
// grid (2, 63) = 126 CTAs -> single wave on 148 SMs.
// SMEM stage (84KB): A 20K @0 | Wh 32K @20480 | Wl 32K @53248. 2 stages = 168KB.
#define STG_BYTES 86016
#define GSMEM (2 * STG_BYTES)

__device__ __forceinline__ void load_stage(
    uint32_t st, const __half* __restrict__ A,
    const __half* __restrict__ Wh, const __half* __restrict__ Wl,
    int kb, int m0, int n0, int K, int M, int tid)
{
#pragma unroll
    for (int t = 0; t < 5; t++) {                 // A: 160 rows x 64 fp16
        int i = tid + t * 256;
        int row = i >> 3, grp = i & 7;
        int gr = m0 + row; if (gr >= M) gr = M - 1;
        size_t off = (size_t)gr * LDA + kb * 64 + grp * 8;
        CP16(st + SWZ128(row * 128 + grp * 16), (const char*)(A + off));
    }
#pragma unroll
    for (int t = 0; t < 8; t++) {                 // W: 256 rows x 64, hi+lo
        int i = tid + t * 256;
        int row = i >> 3, grp = i & 7;
        size_t off = (size_t)(n0 + row) * K + kb * 64 + grp * 8;
        uint32_t sw = SWZ128(row * 128 + grp * 16);
        CP16(st + 20480 + sw, (const char*)(Wh + off));
        CP16(st + 53248 + sw, (const char*)(Wl + off));
    }
}

__global__ void __launch_bounds__(256, 1)
gemm_mma(int asel, int K, int woff, const float* __restrict__ bias,
         int dsel, int M, int doRelu)
{
    extern __shared__ char smem[];
    uint32_t sb = smem_u32(smem);
    const __half* A  = g_act + (size_t)asel * NNODES * LDA;
    const __half* Wh = g_wh + woff;
    const __half* Wl = g_wl + woff;
    __half* D;
    int dstride;
    if (dsel == 2) { D = g_m; dstride = HID; }
    else { D = g_act + (size_t)dsel * NNODES * LDA; dstride = LDA; }

    int tid = threadIdx.x, lane = tid & 31, wid = tid >> 5;
    int warp_m = wid & 1, warp_n = wid >> 1;      // 2 x 4 warps -> 160 x 256
    int m0 = blockIdx.y * 160, n0 = blockIdx.x * 256;

    float c[5][8][4];
#pragma unroll
    for (int mt = 0; mt < 5; mt++)
#pragma unroll
        for (int nt = 0; nt < 8; nt++)
#pragma unroll
            for (int j = 0; j < 4; j++) c[mt][nt][j] = 0.f;

    const int q = lane >> 3, li = lane & 7;
    int NKB = K >> 6;

    load_stage(sb, A, Wh, Wl, 0, m0, n0, K, M, tid);
    CP_COMMIT();

    for (int kb = 0; kb < NKB; kb++) {
        if (kb + 1 < NKB) {
            load_stage(sb + ((kb + 1) & 1) * STG_BYTES, A, Wh, Wl, kb + 1, m0, n0, K, M, tid);
            CP_COMMIT();
            CP_WAIT1();
        } else {
            CP_WAIT0();
        }
        __syncthreads();

        uint32_t st = sb + (kb & 1) * STG_BYTES;
#pragma unroll
        for (int s = 0; s < 4; s++) {
            uint32_t a[5][4], bh[8][2], bl[8][2];
#pragma unroll
            for (int mt = 0; mt < 5; mt++) {
                int row = warp_m * 80 + mt * 16 + ((q & 1) << 3) + li;
                int grp = s * 2 + (q >> 1);
                LDSM4(a[mt], st + SWZ128(row * 128 + grp * 16));
            }
#pragma unroll
            for (int np = 0; np < 4; np++) {
                int nrow = warp_n * 64 + np * 16 + ((q >> 1) << 3) + li;
                int grp = s * 2 + (q & 1);
                uint32_t bd = st + 20480 + SWZ128(nrow * 128 + grp * 16);
                uint32_t r[4];
                LDSM4(r, bd);
                bh[np*2][0] = r[0]; bh[np*2][1] = r[1];
                bh[np*2+1][0] = r[2]; bh[np*2+1][1] = r[3];
                LDSM4(r, bd + 32768);
                bl[np*2][0] = r[0]; bl[np*2][1] = r[1];
                bl[np*2+1][0] = r[2]; bl[np*2+1][1] = r[3];
            }
#pragma unroll
            for (int mt = 0; mt < 5; mt++)
#pragma unroll
                for (int nt = 0; nt < 8; nt++) {
                    MMA_F16(c[mt][nt], a[mt], bh[nt]);
                    MMA_F16(c[mt][nt], a[mt], bl[nt]);
                }
        }
        __syncthreads();
    }

    // epilogue: bias + relu, fp16 stores to staging
    int rlo = lane >> 2;
    int cpos = (lane & 3) * 2;
#pragma unroll
    for (int mt = 0; mt < 5; mt++) {
        int r0 = m0 + warp_m * 80 + mt * 16 + rlo;
#pragma unroll
        for (int nt = 0; nt < 8; nt++) {
            int gc = n0 + warp_n * 64 + nt * 8 + cpos;
            float2 b2 = *(const float2*)(bias + gc);
            float v0 = c[mt][nt][0] + b2.x, v1 = c[mt][nt][1] + b2.y;
            float v2 = c[mt][nt][2] + b2.x, v3 = c[mt][nt][3] + b2.y;
            if (doRelu) {
                v0 = fmaxf(v0, 0.f); v1 = fmaxf(v1, 0.f);
                v2 = fmaxf(v2, 0.f); v3 = fmaxf(v3, 0.f);
            }
            if (r0 < M)
                *(__half2*)(D + (size_t)r0 * dstride + gc) = __floats2half2_rn(v0, v1);
            if (r0 + 8 < M)
                *(__half2*)(D + (size_t)(r0 + 8) * dstride + gc) = __floats2half2_rn(v2, v3);
        }
    }
}

// ---------------- aggregation: stage[cur] cols 512..1023 = sum of msg rows ----------------
__global__ void __launch_bounds__(128)
aggregate_kernel(int cur)
{
    int d = blockIdx.x;
    int t = threadIdx.x;
    int c = t * 4;
    float a0 = 0.f, a1 = 0.f, a2 = 0.f, a3 = 0.f;
    int beg = g_rowptr[d], end = g_rowptr[d + 1];
    for (int j = beg; j < end; j++) {
        int s = g_col[j];
        const __half2* p = (const __half2*)(g_m + (size_t)s * HID + c);
        __half2 u0 = p[0], u1 = p[1];
        float2 f0 = __half22float2(u0), f1 = __half22float2(u1);
        a0 += f0.x; a1 += f0.y; a2 += f1.x; a3 += f1.y;
    }
    size_t o = (size_t)cur * NNODES * LDA + (size_t)d * LDA + 512 + c;
    __half2* p = (__half2*)(g_act + o);
    p[0] = __floats2half2_rn(a0, a1);
    p[1] = __floats2half2_rn(a2, a3);
}

// ---------------- output projection ----------------
__global__ void out_kernel(const float* __restrict__ Wout,
                           const float* __restrict__ bout,
                           float* __restrict__ out, int n, int hsel)
{
    int warp = (blockIdx.x * blockDim.x + threadIdx.x) >> 5;
    int lane = threadIdx.x & 31;
    if (warp >= n) return;
    const __half* hr = g_act + (size_t)hsel * NNODES * LDA + (size_t)warp * LDA;
    float s = 0.f;
#pragma unroll 4
    for (int k = lane; k < HID; k += 32)
        s += __half2float(hr[k]) * Wout[k];
#pragma unroll
    for (int o = 16; o; o >>= 1) s += __shfl_down_sync(0xffffffffu, s, o);
    if (lane == 0) out[warp] = s + bout[0];
}

// ---------------- launcher ----------------
extern "C" void kernel_launch(void* const* d_in, const int* in_sizes, int n_in,
                              void* d_out, int out_size)
{
    const float* x     = (const float*)d_in[0];
    const void*  eidx  = d_in[1];
    const float* W_in  = (const float*)d_in[2];
    const float* b_in  = (const float*)d_in[3];
    const float* msg_W = (const float*)d_in[4];
    const float* msg_b = (const float*)d_in[5];
    const float* upd_W = (const float*)d_in[6];
    const float* upd_b = (const float*)d_in[7];
    const float* W_out = (const float*)d_in[8];
    const float* b_out = (const float*)d_in[9];
    float* out = (float*)d_out;

    // side stream + events for overlapping CSR build and weight conversion
    static cudaStream_t s2 = nullptr;
    static cudaEvent_t eF, e1, e2, e3, e4, e5, e6;
    if (!s2) {
        cudaStreamCreateWithFlags(&s2, cudaStreamNonBlocking);
        cudaEventCreateWithFlags(&eF, cudaEventDisableTiming);
        cudaEventCreateWithFlags(&e1, cudaEventDisableTiming);
        cudaEventCreateWithFlags(&e2, cudaEventDisableTiming);
        cudaEventCreateWithFlags(&e3, cudaEventDisableTiming);
        cudaEventCreateWithFlags(&e4, cudaEventDisableTiming);
        cudaEventCreateWithFlags(&e5, cudaEventDisableTiming);
        cudaEventCreateWithFlags(&e6, cudaEventDisableTiming);
    }

    cudaFuncSetAttribute(gemm_mma, cudaFuncAttributeMaxDynamicSharedMemorySize, GSMEM);

    dim3 wgrid(HID / 32, 0);
    dim3 ggrid(2, (NNODES + 159) / 160);   // (2, 63) = 126 CTAs, single wave

    // ---- fork side stream ----
    cudaEventRecord(eF, 0);
    cudaStreamWaitEvent(s2, eF, 0);

    // s2: weight conversions + CSR build, with progress events
    conv_W<<<dim3(16, INCH / 32), dim3(32, 8), 0, s2>>>(W_in, INCH, WOFF_IN);
    cudaEventRecord(e1, s2);
    conv_W<<<dim3(16, HID / 32), dim3(32, 8), 0, s2>>>(msg_W, HID, WOFF_MSG0);
    cudaEventRecord(e2, s2);
    sniff_kernel<<<1, 256, 0, s2>>>((const unsigned int*)eidx);
    zero_deg_kernel<<<(NNODES + 255) / 256, 256, 0, s2>>>();
    hist_kernel<<<(NEDGES + 255) / 256, 256, 0, s2>>>(eidx, NEDGES);
    scan_kernel<<<1, 1024, 0, s2>>>(NNODES, NEDGES);
    fill_kernel<<<(NEDGES + 255) / 256, 256, 0, s2>>>(eidx, NEDGES);
    cudaEventRecord(e3, s2);
    conv_W<<<dim3(16, 1024 / 32), dim3(32, 8), 0, s2>>>(upd_W, 1024, WOFF_UPD0);
    cudaEventRecord(e4, s2);
    conv_W<<<dim3(16, HID / 32), dim3(32, 8), 0, s2>>>(msg_W + (size_t)HID * HID, HID, WOFF_MSG1);
    cudaEventRecord(e5, s2);
    conv_W<<<dim3(16, 1024 / 32), dim3(32, 8), 0, s2>>>(upd_W + (size_t)2 * HID * HID, 1024, WOFF_UPD1);
    cudaEventRecord(e6, s2);

    // main stream: activation chain
    conv_A<<<(NNODES * (INCH / 4) + 255) / 256, 256>>>(x, 1, INCH, NNODES);

    cudaStreamWaitEvent(0, e1, 0);
    gemm_mma<<<ggrid, 256, GSMEM>>>(/*a=*/1, INCH, WOFF_IN, b_in, /*d=*/0, NNODES, 1);

    // layer 0
    cudaStreamWaitEvent(0, e2, 0);
    gemm_mma<<<ggrid, 256, GSMEM>>>(0, HID, WOFF_MSG0, msg_b, /*d=*/2, NNODES, 1);
    cudaStreamWaitEvent(0, e3, 0);
    aggregate_kernel<<<NNODES, 128>>>(0);
    cudaStreamWaitEvent(0, e4, 0);
    gemm_mma<<<ggrid, 256, GSMEM>>>(0, 1024, WOFF_UPD0, upd_b, /*d=*/1, NNODES, 1);

    // layer 1
    cudaStreamWaitEvent(0, e5, 0);
    gemm_mma<<<ggrid, 256, GSMEM>>>(1, HID, WOFF_MSG1, msg_b + HID, /*d=*/2, NNODES, 1);
    aggregate_kernel<<<NNODES, 128>>>(1);
    cudaStreamWaitEvent(0, e6, 0);
    gemm_mma<<<ggrid, 256, GSMEM>>>(1, 1024, WOFF_UPD1, upd_b + HID, /*d=*/0, NNODES, 1);

    out_kernel<<<(NNODES * 32 + 255) / 256, 256>>>(W_out, b_out, out, NNODES, 0);
}